// round 2
// baseline (speedup 1.0000x reference)
#include <cuda_runtime.h>
#include <math.h>

#define BD 8
#define LLEN 512
#define DD 1024
#define MMCLIP 64
#define RR 129
#define TT 8
#define NROW (BD * LLEN)  // 4096

// ---------------- scratch (device globals; no allocs allowed) ----------------
__device__ __align__(16) float g_h1a[NROW * DD];
__device__ __align__(16) float g_h1b[NROW * DD];
__device__ __align__(16) float g_h2a[NROW * DD];
__device__ __align__(16) float g_h2b[NROW * DD];
__device__ __align__(16) float g_q[NROW * DD];
__device__ __align__(16) float g_k[NROW * DD];
__device__ __align__(16) float g_qrel[NROW * RR];
__device__ __align__(16) float g_sc[BD * LLEN * LLEN];  // scores -> probs in place
__device__ __align__(16) float g_hc[NROW * DD];

// ---------------- init: copy hid into both stream states ----------------
__global__ void copy2_kernel(const float* __restrict__ src,
                             float* __restrict__ d1, float* __restrict__ d2) {
    long n = (long)NROW * DD;
    for (long i = blockIdx.x * (long)blockDim.x + threadIdx.x; i < n;
         i += (long)gridDim.x * blockDim.x) {
        float v = src[i];
        d1[i] = v;
        d2[i] = v;
    }
}

// masks output: om[(b*L + l)*T + t] = (w!=0 && t<=w)
__global__ void masks_kernel(const int* __restrict__ sp, float* __restrict__ om) {
    int idx = blockIdx.x * blockDim.x + threadIdx.x;
    if (idx < BD * LLEN * TT) {
        int t = idx % TT;
        int bl = idx / TT;
        int w = sp[bl];
        om[idx] = (w != 0 && t <= w) ? 1.0f : 0.0f;
    }
}

// =====================================================================
// Unified 128x128-tile SGEMM, 256 threads, 8x8 per thread,
// 2-stage smem double buffering (register prefetch of next K-chunk).
//
//   TB=1:  B is [Mc x K] row-major   (C = A @ B^T)
//   TB=0:  B is [K x Mc] row-major   (C = A @ B)
//   COMBF: A is virtual concat(A, A2) along K, each half lda=DD (K must be 2*DD)
//   RELUF: relu epilogue
//   RAGGED: bound-check Mc on B loads (TB path) and C stores
//
//   C[n,m] = ((sum_k ...) + bias[m]) * scale   [then relu]
// =====================================================================
template <int TB, int COMBF, int RELUF, int RAGGED>
__global__ void __launch_bounds__(256)
gemm_t(const float* __restrict__ A, const float* __restrict__ A2,
       const float* __restrict__ B, const float* __restrict__ bias,
       float* __restrict__ C, int Mc, int K, float scale,
       long sA, long sB, long sC) {
    __shared__ float As[2][16][132];
    __shared__ float Bs[2][16][132];

    int z = blockIdx.z;
    A += (long)z * sA;
    B += (long)z * sB;
    C += (long)z * sC;

    const int rowBase = blockIdx.y * 128;
    const int colBase = blockIdx.x * 128;
    const int tid = threadIdx.x;
    const int tx = tid & 15, ty = tid >> 4;

    float acc[8][8];
#pragma unroll
    for (int i = 0; i < 8; i++)
#pragma unroll
        for (int j = 0; j < 8; j++) acc[i][j] = 0.0f;

    float4 ra[2], rb[2];

    // ---- global -> registers for chunk starting at k0 ----
    auto loadA = [&](int k0) {
#pragma unroll
        for (int l = 0; l < 2; l++) {
            int li = tid + l * 256;
            int r = li >> 2, c4 = li & 3;
            int kk = k0 + c4 * 4;
            const float* Ap = A;
            if (COMBF) {
                if (kk >= DD) { Ap = A2; kk -= DD; }
                ra[l] = *(const float4*)&Ap[(long)(rowBase + r) * DD + kk];
            } else {
                ra[l] = *(const float4*)&Ap[(long)(rowBase + r) * K + kk];
            }
        }
    };
    auto loadB = [&](int k0) {
#pragma unroll
        for (int l = 0; l < 2; l++) {
            int li = tid + l * 256;
            if (TB) {
                int r = li >> 2, c4 = li & 3;
                int col = colBase + r;
                float4 v = make_float4(0.f, 0.f, 0.f, 0.f);
                if (!RAGGED || col < Mc)
                    v = *(const float4*)&B[(long)col * K + k0 + c4 * 4];
                rb[l] = v;
            } else {
                int kk = li >> 5, c = (li & 31) * 4;
                rb[l] = *(const float4*)&B[(long)(k0 + kk) * Mc + colBase + c];
            }
        }
    };
    // ---- registers -> smem buffer buf ----
    auto storeAB = [&](int buf) {
#pragma unroll
        for (int l = 0; l < 2; l++) {
            int li = tid + l * 256;
            int r = li >> 2, c4 = li & 3;
            As[buf][c4 * 4 + 0][r] = ra[l].x;
            As[buf][c4 * 4 + 1][r] = ra[l].y;
            As[buf][c4 * 4 + 2][r] = ra[l].z;
            As[buf][c4 * 4 + 3][r] = ra[l].w;
            if (TB) {
                Bs[buf][c4 * 4 + 0][r] = rb[l].x;
                Bs[buf][c4 * 4 + 1][r] = rb[l].y;
                Bs[buf][c4 * 4 + 2][r] = rb[l].z;
                Bs[buf][c4 * 4 + 3][r] = rb[l].w;
            } else {
                int kk = li >> 5, c = (li & 31) * 4;
                *(float4*)&Bs[buf][kk][c] = rb[l];
            }
        }
    };

    const int nk = K / 16;
    loadA(0);
    loadB(0);
    storeAB(0);
    __syncthreads();

    for (int kt = 0; kt < nk; kt++) {
        const int cur = kt & 1;
        const bool more = (kt + 1 < nk);
        if (more) {
            loadA((kt + 1) * 16);
            loadB((kt + 1) * 16);
        }
        const float(*Asc)[132] = As[cur];
        const float(*Bsc)[132] = Bs[cur];
#pragma unroll
        for (int kk = 0; kk < 16; kk++) {
            float a[8], b[8];
            *(float4*)(a) = *(const float4*)&Asc[kk][ty * 4];
            *(float4*)(a + 4) = *(const float4*)&Asc[kk][64 + ty * 4];
            *(float4*)(b) = *(const float4*)&Bsc[kk][tx * 4];
            *(float4*)(b + 4) = *(const float4*)&Bsc[kk][64 + tx * 4];
#pragma unroll
            for (int i = 0; i < 8; i++)
#pragma unroll
                for (int j = 0; j < 8; j++) acc[i][j] += a[i] * b[j];
        }
        if (more) {
            storeAB(cur ^ 1);
            __syncthreads();
        }
    }

#pragma unroll
    for (int ii = 0; ii < 2; ii++)
#pragma unroll
        for (int i = 0; i < 4; i++) {
            int row = rowBase + ii * 64 + ty * 4 + i;
#pragma unroll
            for (int jj = 0; jj < 2; jj++)
#pragma unroll
                for (int j = 0; j < 4; j++) {
                    int col = colBase + jj * 64 + tx * 4 + j;
                    if (!RAGGED || col < Mc) {
                        float v = acc[ii * 4 + i][jj * 4 + j];
                        if (bias) v += bias[col];
                        v *= scale;
                        if (RELUF) v = fmaxf(v, 0.0f);
                        C[(long)row * Mc + col] = v;
                    }
                }
        }
}

// ---------------- softmax over j with rel-bias + mask; writes probs + output slot ----------------
__global__ void __launch_bounds__(256)
softmax_kernel(float* __restrict__ sc, const float* __restrict__ qrel,
               const int* __restrict__ sp, float* __restrict__ outp, int t) {
    int row = blockIdx.x;  // b*L + i
    int b = row >> 9;
    int i = row & (LLEN - 1);
    int tid = threadIdx.x;

    __shared__ float red[8];

    float v[2];
    float mx = -INFINITY;
#pragma unroll
    for (int u = 0; u < 2; u++) {
        int j = tid + u * 256;
        int d = j - i;
        d = max(-MMCLIP, min(MMCLIP, d));
        float s = sc[(long)row * LLEN + j] + qrel[(long)row * RR + d + MMCLIP];
        int w = sp[b * LLEN + j];
        bool m = (w != 0) && (t <= w);
        s = m ? s : -1e18f;
        v[u] = s;
        mx = fmaxf(mx, s);
    }
#pragma unroll
    for (int o = 16; o; o >>= 1) mx = fmaxf(mx, __shfl_xor_sync(0xffffffffu, mx, o));
    if ((tid & 31) == 0) red[tid >> 5] = mx;
    __syncthreads();
    float bm = red[0];
#pragma unroll
    for (int w2 = 1; w2 < 8; w2++) bm = fmaxf(bm, red[w2]);
    __syncthreads();

    float sum = 0.0f;
#pragma unroll
    for (int u = 0; u < 2; u++) {
        float e = __expf(v[u] - bm);
        v[u] = e;
        sum += e;
    }
#pragma unroll
    for (int o = 16; o; o >>= 1) sum += __shfl_xor_sync(0xffffffffu, sum, o);
    if ((tid & 31) == 0) red[tid >> 5] = sum;
    __syncthreads();
    float bs = 0.0f;
#pragma unroll
    for (int w2 = 0; w2 < 8; w2++) bs += red[w2];
    float inv = 1.0f / bs;

#pragma unroll
    for (int u = 0; u < 2; u++) {
        int j = tid + u * 256;
        float p = v[u] * inv;
        sc[(long)row * LLEN + j] = p;
        outp[((long)row * TT + t) * LLEN + j] = p;  // [b][i][t][j]
    }
}

// ---------------- host orchestration ----------------
extern "C" void kernel_launch(void* const* d_in, const int* in_sizes, int n_in,
                              void* d_out, int out_size) {
    const float* hid    = (const float*)d_in[0];
    const int*   sp     = (const int*)d_in[1];
    const float* Wq_st  = (const float*)d_in[2];
    const float* bq_st  = (const float*)d_in[3];
    const float* Wk_st  = (const float*)d_in[4];
    const float* bk_st  = (const float*)d_in[5];
    const float* rel_st = (const float*)d_in[6];
    const float* Wq_ed  = (const float*)d_in[7];
    const float* bq_ed  = (const float*)d_in[8];
    const float* Wk_ed  = (const float*)d_in[9];
    const float* bk_ed  = (const float*)d_in[10];
    const float* rel_ed = (const float*)d_in[11];
    const float* combW  = (const float*)d_in[12];
    const float* combb  = (const float*)d_in[13];

    float *h1a, *h1b, *h2a, *h2b, *q, *k, *qrel, *sc, *hc;
    cudaGetSymbolAddress((void**)&h1a, g_h1a);
    cudaGetSymbolAddress((void**)&h1b, g_h1b);
    cudaGetSymbolAddress((void**)&h2a, g_h2a);
    cudaGetSymbolAddress((void**)&h2b, g_h2b);
    cudaGetSymbolAddress((void**)&q, g_q);
    cudaGetSymbolAddress((void**)&k, g_k);
    cudaGetSymbolAddress((void**)&qrel, g_qrel);
    cudaGetSymbolAddress((void**)&sc, g_sc);
    cudaGetSymbolAddress((void**)&hc, g_hc);

    float* out_sts = (float*)d_out;
    float* out_eds = out_sts + (long)BD * LLEN * TT * LLEN;
    float* out_m   = out_eds + (long)BD * LLEN * TT * LLEN;

    copy2_kernel<<<256, 256>>>(hid, h1a, h2a);
    masks_kernel<<<(BD * LLEN * TT + 255) / 256, 256>>>(sp, out_m);

    dim3 gN(DD / 128, NROW / 128);           // q,k: 8 x 32
    dim3 gR((RR + 127) / 128, NROW / 128);   // qrel: 2 x 32
    dim3 gS(LLEN / 128, LLEN / 128, BD);     // scores: 4 x 4 x 8
    dim3 gH(DD / 128, LLEN / 128, BD);       // hidc: 8 x 4 x 8
    dim3 gC(DD / 128, NROW / 128);           // comb: 8 x 32

    const float invs = 1.0f / 32.0f;  // 1/sqrt(D)

    for (int t = 0; t < TT; t++) {
        for (int s = 0; s < 2; s++) {
            float* cur = (s == 0) ? ((t & 1) ? h1b : h1a) : ((t & 1) ? h2b : h2a);
            float* nxt = (s == 0) ? ((t & 1) ? h1a : h1b) : ((t & 1) ? h2a : h2b);
            const float* Wq  = (s == 0) ? Wq_st : Wq_ed;
            const float* bq  = (s == 0) ? bq_st : bq_ed;
            const float* Wk  = (s == 0) ? Wk_st : Wk_ed;
            const float* bk  = (s == 0) ? bk_st : bk_ed;
            const float* rel = (s == 0) ? rel_st : rel_ed;
            float* outp = (s == 0) ? out_sts : out_eds;

            // q = (cur @ Wq^T + bq)/32 ; k = cur @ Wk^T + bk
            gemm_t<1, 0, 0, 0><<<gN, 256>>>(cur, nullptr, Wq, bq, q, DD, DD, invs, 0, 0, 0);
            gemm_t<1, 0, 0, 0><<<gN, 256>>>(cur, nullptr, Wk, bk, k, DD, DD, 1.0f, 0, 0, 0);
            // qrel = q @ rel^T  [4096 x 129]
            gemm_t<1, 0, 0, 1><<<gR, 256>>>(q, nullptr, rel, nullptr, qrel, RR, DD, 1.0f, 0, 0, 0);
            // scores[b] = q_b @ k_b^T  (batched over B)
            gemm_t<1, 0, 0, 0><<<gS, 256>>>(q, nullptr, k, nullptr, sc, LLEN, DD, 1.0f,
                                            (long)LLEN * DD, (long)LLEN * DD,
                                            (long)LLEN * LLEN);
            // masked softmax with rel bias; probs into sc and output slab
            softmax_kernel<<<NROW, 256>>>(sc, qrel, sp, outp, t);
            // hidc[b] = attn_b @ hid_b
            gemm_t<0, 0, 0, 0><<<gH, 256>>>(sc, nullptr, cur, nullptr, hc, DD, LLEN,
                                            1.0f, (long)LLEN * LLEN, (long)LLEN * DD,
                                            (long)LLEN * DD);
            // nxt = relu(concat(cur, hidc) @ combW^T + combb)
            gemm_t<1, 1, 1, 0><<<gC, 256>>>(cur, hc, combW, combb, nxt, DD, 2 * DD,
                                            1.0f, 0, 0, 0);
        }
    }
    (void)in_sizes; (void)n_in; (void)out_size;
}

// round 10
// speedup vs baseline: 1.7131x; 1.7131x over previous
#include <cuda_runtime.h>
#include <cuda_bf16.h>
#include <mma.h>
#include <math.h>
#include <stdint.h>

using namespace nvcuda;

#define BD 8
#define LLEN 512
#define DD 1024
#define MMCLIP 64
#define RR 129
#define TT 8
#define NROW (BD * LLEN)  // 4096

// ---------------- scratch (device globals; no allocs allowed) ----------------
__device__ __align__(16) float g_h1a[NROW * DD];
__device__ __align__(16) float g_h1b[NROW * DD];
__device__ __align__(16) float g_h2a[NROW * DD];
__device__ __align__(16) float g_h2b[NROW * DD];
__device__ __align__(16) float g_q[NROW * DD];
__device__ __align__(16) float g_k[NROW * DD];
__device__ __align__(16) float g_qrel[NROW * RR];
__device__ __align__(16) float g_sc[BD * LLEN * LLEN];  // scores -> probs in place
__device__ __align__(16) float g_hc[NROW * DD];

// bf16 hi/lo split: x ~= hi + lo, each bf16 (8 mantissa bits each -> ~16 bits total)
__device__ __forceinline__ void split1(float x, __nv_bfloat16& h, __nv_bfloat16& l) {
    h = __float2bfloat16_rn(x);
    l = __float2bfloat16_rn(x - __bfloat162float(h));
}
__device__ __forceinline__ void split4(float4 v, uint2& h, uint2& lo) {
    __nv_bfloat16 h0, h1, h2, h3, l0, l1, l2, l3;
    split1(v.x, h0, l0);
    split1(v.y, h1, l1);
    split1(v.z, h2, l2);
    split1(v.w, h3, l3);
    h.x = ((uint32_t)__bfloat16_as_ushort(h1) << 16) | __bfloat16_as_ushort(h0);
    h.y = ((uint32_t)__bfloat16_as_ushort(h3) << 16) | __bfloat16_as_ushort(h2);
    lo.x = ((uint32_t)__bfloat16_as_ushort(l1) << 16) | __bfloat16_as_ushort(l0);
    lo.y = ((uint32_t)__bfloat16_as_ushort(l3) << 16) | __bfloat16_as_ushort(l2);
}

// ============================ WMMA tensor GEMM ============================
// 128x128 CTA tile, 256 threads (8 warps, 2x4 warp grid, 64x32 per warp).
// K staged in 32-wide chunks, 2-stage SMEM double buffer w/ register prefetch.
// D += Ahi*Bhi + Alo*Bhi + Ahi*Blo  (fp32 accumulators; lo*lo term negligible)
// TB=1: B is [Mc x K] K-major  (C = A @ B^T)
// TB=0: B is [K x Mc]          (C = A @ B)
// COMBF: A = concat(A, A2) along K (each half lda = DD)
// C[n,m] = ((acc) + bias[m]) * scale  [then relu]
#define KC 32
#define A_LD 40              // 32 + 8 pad (bf16 elems)
#define B0_LD 136            // TB=0: 128 + 8 pad
#define STAGE_B 40960        // Ahi, Alo, Bhi, Blo
#define AHI_O 0
#define ALO_O 10240
#define BHI_O 20480
#define BLO_O 30720
#define SMEM_DYN 81920       // 2 stages; reused as 8x(64x40 f32) epilogue

template <int TB, int COMBF, int RELUF, int RAGGED>
__global__ void __launch_bounds__(256)
tgemm(const float* __restrict__ A, const float* __restrict__ A2,
      const float* __restrict__ B, const float* __restrict__ bias,
      float* __restrict__ C, int Mc, int K, float scale,
      long sA, long sB, long sC) {
    extern __shared__ char smem[];

    const int z = blockIdx.z;
    A += (long)z * sA;
    B += (long)z * sB;
    C += (long)z * sC;

    const int rowBase = blockIdx.y * 128;
    const int colBase = blockIdx.x * 128;
    const int tid = threadIdx.x;
    const int wid = tid >> 5;
    const int wid_r = wid >> 2;   // 0..1  (64-row band)
    const int wid_c = wid & 3;    // 0..3  (32-col band)

    wmma::fragment<wmma::accumulator, 16, 16, 16, float> acc[4][2];
#pragma unroll
    for (int i = 0; i < 4; i++)
#pragma unroll
        for (int j = 0; j < 2; j++) wmma::fill_fragment(acc[i][j], 0.0f);

    float4 ra[4], rb[4];

    auto loadA = [&](int k0) {
#pragma unroll
        for (int l = 0; l < 4; l++) {
            int f = tid + l * 256;         // 0..1023
            int row = f >> 3;              // 0..127
            int kk = k0 + (f & 7) * 4;
            if (COMBF) {
                const float* Ap = A;
                if (kk >= DD) { Ap = A2; kk -= DD; }
                ra[l] = *(const float4*)&Ap[(long)(rowBase + row) * DD + kk];
            } else {
                ra[l] = *(const float4*)&A[(long)(rowBase + row) * K + kk];
            }
        }
    };
    auto loadB = [&](int k0) {
#pragma unroll
        for (int l = 0; l < 4; l++) {
            int f = tid + l * 256;
            if (TB) {
                int row = f >> 3;
                int kk = k0 + (f & 7) * 4;
                int col = colBase + row;
                float4 x = make_float4(0.f, 0.f, 0.f, 0.f);
                if (!RAGGED || col < Mc) x = *(const float4*)&B[(long)col * K + kk];
                rb[l] = x;
            } else {
                int kk = f >> 5;           // 0..31
                int n4 = (f & 31) * 4;     // 0..124
                rb[l] = *(const float4*)&B[(long)(k0 + kk) * Mc + colBase + n4];
            }
        }
    };
    auto storeAB = [&](int s) {
        __nv_bfloat16* ah = (__nv_bfloat16*)(smem + s * STAGE_B + AHI_O);
        __nv_bfloat16* al = (__nv_bfloat16*)(smem + s * STAGE_B + ALO_O);
        __nv_bfloat16* bh = (__nv_bfloat16*)(smem + s * STAGE_B + BHI_O);
        __nv_bfloat16* bl = (__nv_bfloat16*)(smem + s * STAGE_B + BLO_O);
#pragma unroll
        for (int l = 0; l < 4; l++) {
            int f = tid + l * 256;
            {
                int row = f >> 3;
                int k = (f & 7) * 4;
                uint2 h, lo;
                split4(ra[l], h, lo);
                *(uint2*)&ah[row * A_LD + k] = h;
                *(uint2*)&al[row * A_LD + k] = lo;
            }
            if (TB) {
                int row = f >> 3;
                int k = (f & 7) * 4;
                uint2 h, lo;
                split4(rb[l], h, lo);
                *(uint2*)&bh[row * A_LD + k] = h;
                *(uint2*)&bl[row * A_LD + k] = lo;
            } else {
                int kk = f >> 5;
                int n4 = (f & 31) * 4;
                uint2 h, lo;
                split4(rb[l], h, lo);
                *(uint2*)&bh[kk * B0_LD + n4] = h;
                *(uint2*)&bl[kk * B0_LD + n4] = lo;
            }
        }
    };
    auto compute = [&](int s) {
        const __nv_bfloat16* ah = (const __nv_bfloat16*)(smem + s * STAGE_B + AHI_O);
        const __nv_bfloat16* bh = (const __nv_bfloat16*)(smem + s * STAGE_B + BHI_O);
        const __nv_bfloat16* bl = (const __nv_bfloat16*)(smem + s * STAGE_B + BLO_O);
#pragma unroll
        for (int k16 = 0; k16 < 2; k16++) {
            wmma::fragment<wmma::matrix_a, 16, 16, 16, __nv_bfloat16, wmma::row_major> a_h[4], a_l[4];
#pragma unroll
            for (int i = 0; i < 4; i++) {
                const __nv_bfloat16* p = ah + (wid_r * 64 + i * 16) * A_LD + k16 * 16;
                wmma::load_matrix_sync(a_h[i], p, A_LD);
                wmma::load_matrix_sync(a_l[i], p + (ALO_O - AHI_O) / 2, A_LD);
            }
            if (TB) {
                wmma::fragment<wmma::matrix_b, 16, 16, 16, __nv_bfloat16, wmma::col_major> b_h[2], b_l[2];
#pragma unroll
                for (int j = 0; j < 2; j++) {
                    const __nv_bfloat16* p = bh + (wid_c * 32 + j * 16) * A_LD + k16 * 16;
                    wmma::load_matrix_sync(b_h[j], p, A_LD);
                    wmma::load_matrix_sync(b_l[j], bl + (wid_c * 32 + j * 16) * A_LD + k16 * 16, A_LD);
                }
#pragma unroll
                for (int i = 0; i < 4; i++)
#pragma unroll
                    for (int j = 0; j < 2; j++) {
                        wmma::mma_sync(acc[i][j], a_h[i], b_h[j], acc[i][j]);
                        wmma::mma_sync(acc[i][j], a_l[i], b_h[j], acc[i][j]);
                        wmma::mma_sync(acc[i][j], a_h[i], b_l[j], acc[i][j]);
                    }
            } else {
                wmma::fragment<wmma::matrix_b, 16, 16, 16, __nv_bfloat16, wmma::row_major> b_h[2], b_l[2];
#pragma unroll
                for (int j = 0; j < 2; j++) {
                    const __nv_bfloat16* p = bh + k16 * 16 * B0_LD + wid_c * 32 + j * 16;
                    wmma::load_matrix_sync(b_h[j], p, B0_LD);
                    wmma::load_matrix_sync(b_l[j], bl + k16 * 16 * B0_LD + wid_c * 32 + j * 16, B0_LD);
                }
#pragma unroll
                for (int i = 0; i < 4; i++)
#pragma unroll
                    for (int j = 0; j < 2; j++) {
                        wmma::mma_sync(acc[i][j], a_h[i], b_h[j], acc[i][j]);
                        wmma::mma_sync(acc[i][j], a_l[i], b_h[j], acc[i][j]);
                        wmma::mma_sync(acc[i][j], a_h[i], b_l[j], acc[i][j]);
                    }
            }
        }
    };

    const int nk = K / KC;
    loadA(0);
    loadB(0);
    storeAB(0);
    __syncthreads();
    for (int kt = 0; kt < nk; kt++) {
        const int s = kt & 1;
        const bool more = (kt + 1 < nk);
        if (more) {
            loadA((kt + 1) * KC);
            loadB((kt + 1) * KC);
        }
        compute(s);
        if (more) {
            storeAB(s ^ 1);
        }
        __syncthreads();
    }

    // ---- epilogue: dump accumulators to SMEM, then coalesced bias/scale/relu ----
    float* eb = (float*)smem;
    float* wreg = eb + wid * (64 * 40);
#pragma unroll
    for (int i = 0; i < 4; i++)
#pragma unroll
        for (int j = 0; j < 2; j++)
            wmma::store_matrix_sync(wreg + i * 16 * 40 + j * 16, acc[i][j], 40,
                                    wmma::mem_row_major);
    __syncthreads();

#pragma unroll 4
    for (int it = 0; it < 64; it++) {
        int idx = tid + it * 256;          // 0..16383
        int gr = idx >> 7;                 // 0..127
        int gc = idx & 127;                // 0..127
        int w = (gr >> 6) * 4 + (gc >> 5);
        float val = eb[w * (64 * 40) + (gr & 63) * 40 + (gc & 31)];
        int col = colBase + gc;
        if (!RAGGED || col < Mc) {
            if (bias) val += bias[col];
            val *= scale;
            if (RELUF) val = fmaxf(val, 0.0f);
            C[(long)(rowBase + gr) * Mc + col] = val;
        }
    }
}

// ---------------- small kernels ----------------
__global__ void copy2_kernel(const float* __restrict__ src,
                             float* __restrict__ d1, float* __restrict__ d2) {
    long n = (long)NROW * DD;
    for (long i = blockIdx.x * (long)blockDim.x + threadIdx.x; i < n;
         i += (long)gridDim.x * blockDim.x) {
        float v = src[i];
        d1[i] = v;
        d2[i] = v;
    }
}

__global__ void masks_kernel(const int* __restrict__ sp, float* __restrict__ om) {
    int idx = blockIdx.x * blockDim.x + threadIdx.x;
    if (idx < BD * LLEN * TT) {
        int t = idx % TT;
        int bl = idx / TT;
        int w = sp[bl];
        om[idx] = (w != 0 && t <= w) ? 1.0f : 0.0f;
    }
}

__global__ void __launch_bounds__(256)
softmax_kernel(float* __restrict__ sc, const float* __restrict__ qrel,
               const int* __restrict__ sp, float* __restrict__ outp, int t) {
    int row = blockIdx.x;  // b*L + i
    int b = row >> 9;
    int i = row & (LLEN - 1);
    int tid = threadIdx.x;

    __shared__ float red[8];

    float v[2];
    float mx = -INFINITY;
#pragma unroll
    for (int u = 0; u < 2; u++) {
        int j = tid + u * 256;
        int d = j - i;
        d = max(-MMCLIP, min(MMCLIP, d));
        float s = sc[(long)row * LLEN + j] + qrel[(long)row * RR + d + MMCLIP];
        int w = sp[b * LLEN + j];
        bool m = (w != 0) && (t <= w);
        s = m ? s : -1e18f;
        v[u] = s;
        mx = fmaxf(mx, s);
    }
#pragma unroll
    for (int o = 16; o; o >>= 1) mx = fmaxf(mx, __shfl_xor_sync(0xffffffffu, mx, o));
    if ((tid & 31) == 0) red[tid >> 5] = mx;
    __syncthreads();
    float bm = red[0];
#pragma unroll
    for (int w2 = 1; w2 < 8; w2++) bm = fmaxf(bm, red[w2]);
    __syncthreads();

    float sum = 0.0f;
#pragma unroll
    for (int u = 0; u < 2; u++) {
        float e = __expf(v[u] - bm);
        v[u] = e;
        sum += e;
    }
#pragma unroll
    for (int o = 16; o; o >>= 1) sum += __shfl_xor_sync(0xffffffffu, sum, o);
    if ((tid & 31) == 0) red[tid >> 5] = sum;
    __syncthreads();
    float bs = 0.0f;
#pragma unroll
    for (int w2 = 0; w2 < 8; w2++) bs += red[w2];
    float inv = 1.0f / bs;

#pragma unroll
    for (int u = 0; u < 2; u++) {
        int j = tid + u * 256;
        float p = v[u] * inv;
        sc[(long)row * LLEN + j] = p;
        outp[((long)row * TT + t) * LLEN + j] = p;  // [b][i][t][j]
    }
}

// ---------------- host orchestration ----------------
extern "C" void kernel_launch(void* const* d_in, const int* in_sizes, int n_in,
                              void* d_out, int out_size) {
    const float* hid    = (const float*)d_in[0];
    const int*   sp     = (const int*)d_in[1];
    const float* Wq_st  = (const float*)d_in[2];
    const float* bq_st  = (const float*)d_in[3];
    const float* Wk_st  = (const float*)d_in[4];
    const float* bk_st  = (const float*)d_in[5];
    const float* rel_st = (const float*)d_in[6];
    const float* Wq_ed  = (const float*)d_in[7];
    const float* bq_ed  = (const float*)d_in[8];
    const float* Wk_ed  = (const float*)d_in[9];
    const float* bk_ed  = (const float*)d_in[10];
    const float* rel_ed = (const float*)d_in[11];
    const float* combW  = (const float*)d_in[12];
    const float* combb  = (const float*)d_in[13];

    float *h1a, *h1b, *h2a, *h2b, *q, *k, *qrel, *sc, *hc;
    cudaGetSymbolAddress((void**)&h1a, g_h1a);
    cudaGetSymbolAddress((void**)&h1b, g_h1b);
    cudaGetSymbolAddress((void**)&h2a, g_h2a);
    cudaGetSymbolAddress((void**)&h2b, g_h2b);
    cudaGetSymbolAddress((void**)&q, g_q);
    cudaGetSymbolAddress((void**)&k, g_k);
    cudaGetSymbolAddress((void**)&qrel, g_qrel);
    cudaGetSymbolAddress((void**)&sc, g_sc);
    cudaGetSymbolAddress((void**)&hc, g_hc);

    cudaFuncSetAttribute(tgemm<1, 0, 0, 0>, cudaFuncAttributeMaxDynamicSharedMemorySize, SMEM_DYN);
    cudaFuncSetAttribute(tgemm<1, 0, 0, 1>, cudaFuncAttributeMaxDynamicSharedMemorySize, SMEM_DYN);
    cudaFuncSetAttribute(tgemm<0, 0, 0, 0>, cudaFuncAttributeMaxDynamicSharedMemorySize, SMEM_DYN);
    cudaFuncSetAttribute(tgemm<1, 1, 1, 0>, cudaFuncAttributeMaxDynamicSharedMemorySize, SMEM_DYN);

    float* out_sts = (float*)d_out;
    float* out_eds = out_sts + (long)BD * LLEN * TT * LLEN;
    float* out_m   = out_eds + (long)BD * LLEN * TT * LLEN;

    copy2_kernel<<<256, 256>>>(hid, h1a, h2a);
    masks_kernel<<<(BD * LLEN * TT + 255) / 256, 256>>>(sp, out_m);

    dim3 gN(DD / 128, NROW / 128);           // q,k: 8 x 32
    dim3 gR((RR + 127) / 128, NROW / 128);   // qrel: 2 x 32
    dim3 gS(LLEN / 128, LLEN / 128, BD);     // scores: 4 x 4 x 8
    dim3 gH(DD / 128, LLEN / 128, BD);       // hidc: 8 x 4 x 8
    dim3 gC(DD / 128, NROW / 128);           // comb: 8 x 32

    const float invs = 1.0f / 32.0f;  // 1/sqrt(D)

    for (int t = 0; t < TT; t++) {
        for (int s = 0; s < 2; s++) {
            float* cur = (s == 0) ? ((t & 1) ? h1b : h1a) : ((t & 1) ? h2b : h2a);
            float* nxt = (s == 0) ? ((t & 1) ? h1a : h1b) : ((t & 1) ? h2a : h2b);
            const float* Wq  = (s == 0) ? Wq_st : Wq_ed;
            const float* bq  = (s == 0) ? bq_st : bq_ed;
            const float* Wk  = (s == 0) ? Wk_st : Wk_ed;
            const float* bk  = (s == 0) ? bk_st : bk_ed;
            const float* rel = (s == 0) ? rel_st : rel_ed;
            float* outp = (s == 0) ? out_sts : out_eds;

            // q = (cur @ Wq^T + bq)/32 ; k = cur @ Wk^T + bk
            tgemm<1, 0, 0, 0><<<gN, 256, SMEM_DYN>>>(cur, nullptr, Wq, bq, q, DD, DD, invs, 0, 0, 0);
            tgemm<1, 0, 0, 0><<<gN, 256, SMEM_DYN>>>(cur, nullptr, Wk, bk, k, DD, DD, 1.0f, 0, 0, 0);
            // qrel = q @ rel^T  [4096 x 129]
            tgemm<1, 0, 0, 1><<<gR, 256, SMEM_DYN>>>(q, nullptr, rel, nullptr, qrel, RR, DD, 1.0f, 0, 0, 0);
            // scores[b] = q_b @ k_b^T
            tgemm<1, 0, 0, 0><<<gS, 256, SMEM_DYN>>>(q, nullptr, k, nullptr, sc, LLEN, DD, 1.0f,
                                                     (long)LLEN * DD, (long)LLEN * DD,
                                                     (long)LLEN * LLEN);
            softmax_kernel<<<NROW, 256>>>(sc, qrel, sp, outp, t);
            // hidc[b] = attn_b @ hid_b  (NN)
            tgemm<0, 0, 0, 0><<<gH, 256, SMEM_DYN>>>(sc, nullptr, cur, nullptr, hc, DD, LLEN,
                                                     1.0f, (long)LLEN * LLEN, (long)LLEN * DD,
                                                     (long)LLEN * DD);
            // nxt = relu(concat(cur, hidc) @ combW^T + combb)
            tgemm<1, 1, 1, 0><<<gC, 256, SMEM_DYN>>>(cur, hc, combW, combb, nxt, DD, 2 * DD,
                                                     1.0f, 0, 0, 0);
        }
    }
    (void)in_sizes; (void)n_in; (void)out_size;
}

// round 12
// speedup vs baseline: 2.4459x; 1.4277x over previous
#include <cuda_runtime.h>
#include <cuda_bf16.h>
#include <mma.h>
#include <math.h>
#include <stdint.h>

using namespace nvcuda;
typedef __nv_bfloat16 bf16;

#define BD 8
#define LLEN 512
#define DD 1024
#define MMCLIP 64
#define RR 129
#define TT 8
#define NROW (BD * LLEN)      // 4096
#define NSTATE (NROW * DD)    // 4M elems
#define NPROB (BD * LLEN * LLEN)

// ---------------- scratch (device globals; no allocs allowed) ----------------
// split bf16 state + activations
__device__ __align__(16) bf16 g_h1a_hi[NSTATE], g_h1a_lo[NSTATE];
__device__ __align__(16) bf16 g_h1b_hi[NSTATE], g_h1b_lo[NSTATE];
__device__ __align__(16) bf16 g_h2a_hi[NSTATE], g_h2a_lo[NSTATE];
__device__ __align__(16) bf16 g_h2b_hi[NSTATE], g_h2b_lo[NSTATE];
__device__ __align__(16) bf16 g_q_hi[NSTATE], g_q_lo[NSTATE];
__device__ __align__(16) bf16 g_k_hi[NSTATE], g_k_lo[NSTATE];
__device__ __align__(16) bf16 g_hc_hi[NSTATE], g_hc_lo[NSTATE];
__device__ __align__(16) bf16 g_p_hi[NPROB], g_p_lo[NPROB];
// split weights (index s*stride for st/ed)
__device__ __align__(16) bf16 g_wq_hi[2 * DD * DD], g_wq_lo[2 * DD * DD];
__device__ __align__(16) bf16 g_wk_hi[2 * DD * DD], g_wk_lo[2 * DD * DD];
__device__ __align__(16) bf16 g_rel_hi[2 * RR * DD], g_rel_lo[2 * RR * DD];
__device__ __align__(16) bf16 g_cw_hi[DD * 2 * DD], g_cw_lo[DD * 2 * DD];
// fp32 intermediates
__device__ __align__(16) float g_sc[NPROB];
__device__ __align__(16) float g_qrel[NROW * RR];

// ---------------- cp.async helpers ----------------
__device__ __forceinline__ void cp16(uint32_t dst, const void* src, bool pred) {
    int sz = pred ? 16 : 0;
    asm volatile("cp.async.cg.shared.global [%0], [%1], 16, %2;\n"
                 :: "r"(dst), "l"(src), "r"(sz));
}
#define CP_COMMIT() asm volatile("cp.async.commit_group;\n" ::: "memory")
#define CP_WAIT(n) asm volatile("cp.async.wait_group %0;\n" :: "n"(n) : "memory")

__device__ __forceinline__ void split_store(float v, bf16* hi, bf16* lo, long o) {
    bf16 h = __float2bfloat16_rn(v);
    hi[o] = h;
    lo[o] = __float2bfloat16_rn(v - __bfloat162float(h));
}

// ============================ WMMA tensor GEMM ============================
// 128x128 CTA tile, 256 threads (8 warps, 2x4 grid, 64x32 per warp), 2 CTAs/SM.
// All operands pre-split bf16 hi/lo; cp.async 2-stage double buffer, KC=32.
// D += Ahi*Bhi + Alo*Bhi + Ahi*Blo  (fp32 accumulators)
// TB=1: B is [Mc x K] K-major (C = A@B^T); TB=0: B is [K x Mc] (C = A@B)
// COMBF: A = concat(A, A2) along K (each half lda = DD)
// OSPLIT=1: write Chi/Clo bf16 split; else write C fp32.
// out = ((acc) + bias[m]) * scale [then relu]
#define KC 32
#define A_LD 40              // bf16 elems (32+8 pad); row = 80 B
#define B0_LD 136            // TB=0 (128+8); row = 272 B
#define STAGE_B 40960
#define AHI_O 0
#define ALO_O 10240
#define BHI_O 20480
#define BLO_O 30720
#define SMEM_DYN 81920       // 2 stages; reused as 8x(64x40 f32) epilogue

template <int TB, int COMBF, int RELUF, int RAGGED, int OSPLIT>
__global__ void __launch_bounds__(256, 2)
tgemm(const bf16* __restrict__ Ahi, const bf16* __restrict__ Alo,
      const bf16* __restrict__ A2hi, const bf16* __restrict__ A2lo,
      const bf16* __restrict__ Bhi, const bf16* __restrict__ Blo,
      const float* __restrict__ bias,
      float* __restrict__ C, bf16* __restrict__ Chi, bf16* __restrict__ Clo,
      int Mc, int K, float scale, long sA, long sB, long sC) {
    extern __shared__ char smem[];
    const uint32_t sbase = (uint32_t)__cvta_generic_to_shared(smem);

    const int z = blockIdx.z;
    Ahi += (long)z * sA;
    Alo += (long)z * sA;
    Bhi += (long)z * sB;
    Blo += (long)z * sB;
    if (OSPLIT) { Chi += (long)z * sC; Clo += (long)z * sC; }
    else        { C += (long)z * sC; }

    const int rowBase = blockIdx.y * 128;
    const int colBase = blockIdx.x * 128;
    const int tid = threadIdx.x;
    const int wid = tid >> 5;
    const int wid_r = wid >> 2;   // 0..1
    const int wid_c = wid & 3;    // 0..3

    wmma::fragment<wmma::accumulator, 16, 16, 16, float> acc[4][2];
#pragma unroll
    for (int i = 0; i < 4; i++)
#pragma unroll
        for (int j = 0; j < 2; j++) wmma::fill_fragment(acc[i][j], 0.0f);

    auto issue = [&](int c) {
        const int k0 = c * KC;
        const uint32_t base = sbase + (c & 1) * STAGE_B;
#pragma unroll
        for (int l = 0; l < 2; l++) {
            int f = tid + l * 256;          // 0..511
            // ---- A: 128 rows x 64B (hi & lo) ----
            {
                int row = f >> 2, seg = f & 3;
                int kk = k0 + seg * 8;
                const bf16 *ph = Ahi, *pl = Alo;
                int lda = K;
                if (COMBF) {
                    lda = DD;
                    if (kk >= DD) { ph = A2hi; pl = A2lo; kk -= DD; }
                }
                long off = (long)(rowBase + row) * lda + kk;
                uint32_t d = base + AHI_O + row * (A_LD * 2) + seg * 16;
                cp16(d, ph + off, true);
                cp16(d + (ALO_O - AHI_O), pl + off, true);
            }
            // ---- B ----
            if (TB) {
                int row = f >> 2, seg = f & 3;
                int col = colBase + row;
                bool p = (!RAGGED) || (col < Mc);
                long off = p ? ((long)col * K + k0 + seg * 8) : 0;
                uint32_t d = base + BHI_O + row * (A_LD * 2) + seg * 16;
                cp16(d, Bhi + off, p);
                cp16(d + (BLO_O - BHI_O), Blo + off, p);
            } else {
                int kk = f >> 4, seg = f & 15;   // 32 k-rows x 256B
                long off = (long)(k0 + kk) * Mc + colBase + seg * 8;
                uint32_t d = base + BHI_O + kk * (B0_LD * 2) + seg * 16;
                cp16(d, Bhi + off, true);
                cp16(d + (BLO_O - BHI_O), Blo + off, true);
            }
        }
        CP_COMMIT();
    };

    auto compute = [&](int s) {
        const bf16* ah = (const bf16*)(smem + s * STAGE_B + AHI_O);
        const bf16* al = (const bf16*)(smem + s * STAGE_B + ALO_O);
        const bf16* bh = (const bf16*)(smem + s * STAGE_B + BHI_O);
        const bf16* bl = (const bf16*)(smem + s * STAGE_B + BLO_O);
#pragma unroll
        for (int k16 = 0; k16 < 2; k16++) {
            wmma::fragment<wmma::matrix_a, 16, 16, 16, bf16, wmma::row_major> a_h[4], a_l[4];
#pragma unroll
            for (int i = 0; i < 4; i++) {
                int r0 = (wid_r * 64 + i * 16) * A_LD + k16 * 16;
                wmma::load_matrix_sync(a_h[i], ah + r0, A_LD);
                wmma::load_matrix_sync(a_l[i], al + r0, A_LD);
            }
            if (TB) {
                wmma::fragment<wmma::matrix_b, 16, 16, 16, bf16, wmma::col_major> b_h[2], b_l[2];
#pragma unroll
                for (int j = 0; j < 2; j++) {
                    int r0 = (wid_c * 32 + j * 16) * A_LD + k16 * 16;
                    wmma::load_matrix_sync(b_h[j], bh + r0, A_LD);
                    wmma::load_matrix_sync(b_l[j], bl + r0, A_LD);
                }
#pragma unroll
                for (int i = 0; i < 4; i++)
#pragma unroll
                    for (int j = 0; j < 2; j++) {
                        wmma::mma_sync(acc[i][j], a_h[i], b_h[j], acc[i][j]);
                        wmma::mma_sync(acc[i][j], a_l[i], b_h[j], acc[i][j]);
                        wmma::mma_sync(acc[i][j], a_h[i], b_l[j], acc[i][j]);
                    }
            } else {
                wmma::fragment<wmma::matrix_b, 16, 16, 16, bf16, wmma::row_major> b_h[2], b_l[2];
#pragma unroll
                for (int j = 0; j < 2; j++) {
                    int r0 = k16 * 16 * B0_LD + wid_c * 32 + j * 16;
                    wmma::load_matrix_sync(b_h[j], bh + r0, B0_LD);
                    wmma::load_matrix_sync(b_l[j], bl + r0, B0_LD);
                }
#pragma unroll
                for (int i = 0; i < 4; i++)
#pragma unroll
                    for (int j = 0; j < 2; j++) {
                        wmma::mma_sync(acc[i][j], a_h[i], b_h[j], acc[i][j]);
                        wmma::mma_sync(acc[i][j], a_l[i], b_h[j], acc[i][j]);
                        wmma::mma_sync(acc[i][j], a_h[i], b_l[j], acc[i][j]);
                    }
            }
        }
    };

    const int nk = K / KC;
    issue(0);
    for (int c = 0; c < nk; c++) {
        if (c + 1 < nk) {
            issue(c + 1);
            CP_WAIT(1);
        } else {
            CP_WAIT(0);
        }
        __syncthreads();
        compute(c & 1);
        __syncthreads();
    }

    // ---- epilogue: accumulators -> SMEM -> coalesced out ----
    float* eb = (float*)smem;
    float* wreg = eb + wid * (64 * 40);
#pragma unroll
    for (int i = 0; i < 4; i++)
#pragma unroll
        for (int j = 0; j < 2; j++)
            wmma::store_matrix_sync(wreg + i * 16 * 40 + j * 16, acc[i][j], 40,
                                    wmma::mem_row_major);
    __syncthreads();

#pragma unroll 4
    for (int it = 0; it < 64; it++) {
        int idx = tid + it * 256;
        int gr = idx >> 7;
        int gc = idx & 127;
        int w = (gr >> 6) * 4 + (gc >> 5);
        float val = eb[w * (64 * 40) + (gr & 63) * 40 + (gc & 31)];
        int col = colBase + gc;
        if (!RAGGED || col < Mc) {
            if (bias) val += bias[col];
            val *= scale;
            if (RELUF) val = fmaxf(val, 0.0f);
            long o = (long)(rowBase + gr) * Mc + col;
            if (OSPLIT) split_store(val, Chi, Clo, o);
            else C[o] = val;
        }
    }
}

// ---------------- small kernels ----------------
__global__ void split_kernel(const float* __restrict__ src, bf16* __restrict__ hi,
                             bf16* __restrict__ lo, int n) {
    int i = blockIdx.x * blockDim.x + threadIdx.x;
    if (i < n) {
        float x = src[i];
        bf16 h = __float2bfloat16_rn(x);
        hi[i] = h;
        lo[i] = __float2bfloat16_rn(x - __bfloat162float(h));
    }
}

// hid -> both stream states, split
__global__ void split2_kernel(const float* __restrict__ src,
                              bf16* __restrict__ h1h, bf16* __restrict__ h1l,
                              bf16* __restrict__ h2h, bf16* __restrict__ h2l) {
    long n = (long)NSTATE;
    for (long i = blockIdx.x * (long)blockDim.x + threadIdx.x; i < n;
         i += (long)gridDim.x * blockDim.x) {
        float x = src[i];
        bf16 h = __float2bfloat16_rn(x);
        bf16 l = __float2bfloat16_rn(x - __bfloat162float(h));
        h1h[i] = h;
        h1l[i] = l;
        h2h[i] = h;
        h2l[i] = l;
    }
}

__global__ void masks_kernel(const int* __restrict__ sp, float* __restrict__ om) {
    int idx = blockIdx.x * blockDim.x + threadIdx.x;
    if (idx < BD * LLEN * TT) {
        int t = idx % TT;
        int bl = idx / TT;
        int w = sp[bl];
        om[idx] = (w != 0 && t <= w) ? 1.0f : 0.0f;
    }
}

__global__ void __launch_bounds__(256)
softmax_kernel(const float* __restrict__ sc, const float* __restrict__ qrel,
               const int* __restrict__ sp, float* __restrict__ outp,
               bf16* __restrict__ phi, bf16* __restrict__ plo, int t) {
    int row = blockIdx.x;  // b*L + i
    int b = row >> 9;
    int i = row & (LLEN - 1);
    int tid = threadIdx.x;

    __shared__ float red[8];

    float v[2];
    float mx = -INFINITY;
#pragma unroll
    for (int u = 0; u < 2; u++) {
        int j = tid + u * 256;
        int d = j - i;
        d = max(-MMCLIP, min(MMCLIP, d));
        float s = sc[(long)row * LLEN + j] + qrel[(long)row * RR + d + MMCLIP];
        int w = sp[b * LLEN + j];
        bool m = (w != 0) && (t <= w);
        s = m ? s : -1e18f;
        v[u] = s;
        mx = fmaxf(mx, s);
    }
#pragma unroll
    for (int o = 16; o; o >>= 1) mx = fmaxf(mx, __shfl_xor_sync(0xffffffffu, mx, o));
    if ((tid & 31) == 0) red[tid >> 5] = mx;
    __syncthreads();
    float bm = red[0];
#pragma unroll
    for (int w2 = 1; w2 < 8; w2++) bm = fmaxf(bm, red[w2]);
    __syncthreads();

    float sum = 0.0f;
#pragma unroll
    for (int u = 0; u < 2; u++) {
        float e = __expf(v[u] - bm);
        v[u] = e;
        sum += e;
    }
#pragma unroll
    for (int o = 16; o; o >>= 1) sum += __shfl_xor_sync(0xffffffffu, sum, o);
    if ((tid & 31) == 0) red[tid >> 5] = sum;
    __syncthreads();
    float bs = 0.0f;
#pragma unroll
    for (int w2 = 0; w2 < 8; w2++) bs += red[w2];
    float inv = 1.0f / bs;

#pragma unroll
    for (int u = 0; u < 2; u++) {
        int j = tid + u * 256;
        float p = v[u] * inv;
        outp[((long)row * TT + t) * LLEN + j] = p;  // [b][i][t][j]
        long o = (long)row * LLEN + j;
        bf16 h = __float2bfloat16_rn(p);
        phi[o] = h;
        plo[o] = __float2bfloat16_rn(p - __bfloat162float(h));
    }
}

// ---------------- host orchestration ----------------
#define GSYM(var, sym) cudaGetSymbolAddress((void**)&var, sym)

extern "C" void kernel_launch(void* const* d_in, const int* in_sizes, int n_in,
                              void* d_out, int out_size) {
    const float* hid    = (const float*)d_in[0];
    const int*   sp     = (const int*)d_in[1];
    const float* Wq_st  = (const float*)d_in[2];
    const float* bq_st  = (const float*)d_in[3];
    const float* Wk_st  = (const float*)d_in[4];
    const float* bk_st  = (const float*)d_in[5];
    const float* rel_st = (const float*)d_in[6];
    const float* Wq_ed  = (const float*)d_in[7];
    const float* bq_ed  = (const float*)d_in[8];
    const float* Wk_ed  = (const float*)d_in[9];
    const float* bk_ed  = (const float*)d_in[10];
    const float* rel_ed = (const float*)d_in[11];
    const float* combW  = (const float*)d_in[12];
    const float* combb  = (const float*)d_in[13];

    bf16 *h1ah, *h1al, *h1bh, *h1bl, *h2ah, *h2al, *h2bh, *h2bl;
    bf16 *qh, *ql, *kh, *kl, *hch, *hcl, *ph, *pl;
    bf16 *wqh, *wql, *wkh, *wkl, *relh, *rell, *cwh, *cwl;
    float *sc, *qrel;
    GSYM(h1ah, g_h1a_hi); GSYM(h1al, g_h1a_lo);
    GSYM(h1bh, g_h1b_hi); GSYM(h1bl, g_h1b_lo);
    GSYM(h2ah, g_h2a_hi); GSYM(h2al, g_h2a_lo);
    GSYM(h2bh, g_h2b_hi); GSYM(h2bl, g_h2b_lo);
    GSYM(qh, g_q_hi); GSYM(ql, g_q_lo);
    GSYM(kh, g_k_hi); GSYM(kl, g_k_lo);
    GSYM(hch, g_hc_hi); GSYM(hcl, g_hc_lo);
    GSYM(ph, g_p_hi); GSYM(pl, g_p_lo);
    GSYM(wqh, g_wq_hi); GSYM(wql, g_wq_lo);
    GSYM(wkh, g_wk_hi); GSYM(wkl, g_wk_lo);
    GSYM(relh, g_rel_hi); GSYM(rell, g_rel_lo);
    GSYM(cwh, g_cw_hi); GSYM(cwl, g_cw_lo);
    GSYM(sc, g_sc); GSYM(qrel, g_qrel);

    cudaFuncSetAttribute(tgemm<1, 0, 0, 0, 1>, cudaFuncAttributeMaxDynamicSharedMemorySize, SMEM_DYN);
    cudaFuncSetAttribute(tgemm<1, 0, 0, 1, 0>, cudaFuncAttributeMaxDynamicSharedMemorySize, SMEM_DYN);
    cudaFuncSetAttribute(tgemm<1, 0, 0, 0, 0>, cudaFuncAttributeMaxDynamicSharedMemorySize, SMEM_DYN);
    cudaFuncSetAttribute(tgemm<0, 0, 0, 0, 1>, cudaFuncAttributeMaxDynamicSharedMemorySize, SMEM_DYN);
    cudaFuncSetAttribute(tgemm<1, 1, 1, 0, 1>, cudaFuncAttributeMaxDynamicSharedMemorySize, SMEM_DYN);

    float* out_sts = (float*)d_out;
    float* out_eds = out_sts + (long)BD * LLEN * TT * LLEN;
    float* out_m   = out_eds + (long)BD * LLEN * TT * LLEN;

    // one-time splits (graph-captured; deterministic)
    const int DW = DD * DD;
    split2_kernel<<<256, 256>>>(hid, h1ah, h1al, h2ah, h2al);
    masks_kernel<<<(BD * LLEN * TT + 255) / 256, 256>>>(sp, out_m);
    split_kernel<<<(DW + 255) / 256, 256>>>(Wq_st, wqh, wql, DW);
    split_kernel<<<(DW + 255) / 256, 256>>>(Wq_ed, wqh + DW, wql + DW, DW);
    split_kernel<<<(DW + 255) / 256, 256>>>(Wk_st, wkh, wkl, DW);
    split_kernel<<<(DW + 255) / 256, 256>>>(Wk_ed, wkh + DW, wkl + DW, DW);
    split_kernel<<<(RR * DD + 255) / 256, 256>>>(rel_st, relh, rell, RR * DD);
    split_kernel<<<(RR * DD + 255) / 256, 256>>>(rel_ed, relh + RR * DD, rell + RR * DD, RR * DD);
    split_kernel<<<(2 * DW + 255) / 256, 256>>>(combW, cwh, cwl, 2 * DW);

    dim3 gN(DD / 128, NROW / 128);           // 8 x 32 = 256
    dim3 gR((RR + 127) / 128, NROW / 128);   // 2 x 32
    dim3 gS(LLEN / 128, LLEN / 128, BD);     // 4 x 4 x 8
    dim3 gH(DD / 128, LLEN / 128, BD);       // 8 x 4 x 8
    dim3 gC(DD / 128, NROW / 128);           // 8 x 32

    const float invs = 1.0f / 32.0f;

    for (int t = 0; t < TT; t++) {
        for (int s = 0; s < 2; s++) {
            bf16 *curh, *curl, *nxth, *nxtl;
            if (s == 0) {
                curh = (t & 1) ? h1bh : h1ah; curl = (t & 1) ? h1bl : h1al;
                nxth = (t & 1) ? h1ah : h1bh; nxtl = (t & 1) ? h1al : h1bl;
            } else {
                curh = (t & 1) ? h2bh : h2ah; curl = (t & 1) ? h2bl : h2al;
                nxth = (t & 1) ? h2ah : h2bh; nxtl = (t & 1) ? h2al : h2bl;
            }
            const bf16* Wqh = wqh + s * DW;  const bf16* Wql = wql + s * DW;
            const bf16* Wkh = wkh + s * DW;  const bf16* Wkl = wkl + s * DW;
            const bf16* Rh  = relh + s * RR * DD;
            const bf16* Rl  = rell + s * RR * DD;
            const float* bq = (s == 0) ? bq_st : bq_ed;
            const float* bk = (s == 0) ? bk_st : bk_ed;
            float* outp = (s == 0) ? out_sts : out_eds;

            // q = (cur @ Wq^T + bq)/32  -> split
            tgemm<1, 0, 0, 0, 1><<<gN, 256, SMEM_DYN>>>(
                curh, curl, nullptr, nullptr, Wqh, Wql, bq,
                nullptr, qh, ql, DD, DD, invs, 0, 0, 0);
            // k = cur @ Wk^T + bk  -> split
            tgemm<1, 0, 0, 0, 1><<<gN, 256, SMEM_DYN>>>(
                curh, curl, nullptr, nullptr, Wkh, Wkl, bk,
                nullptr, kh, kl, DD, DD, 1.0f, 0, 0, 0);
            // qrel = q @ rel^T  (fp32)
            tgemm<1, 0, 0, 1, 0><<<gR, 256, SMEM_DYN>>>(
                qh, ql, nullptr, nullptr, Rh, Rl, nullptr,
                qrel, nullptr, nullptr, RR, DD, 1.0f, 0, 0, 0);
            // scores[b] = q_b @ k_b^T  (fp32)
            tgemm<1, 0, 0, 0, 0><<<gS, 256, SMEM_DYN>>>(
                qh, ql, nullptr, nullptr, kh, kl, nullptr,
                sc, nullptr, nullptr, LLEN, DD, 1.0f,
                (long)LLEN * DD, (long)LLEN * DD, (long)LLEN * LLEN);
            // softmax -> probs split + output slab
            softmax_kernel<<<NROW, 256>>>(sc, qrel, sp, outp, ph, pl, t);
            // hidc[b] = probs_b @ cur_b  -> split
            tgemm<0, 0, 0, 0, 1><<<gH, 256, SMEM_DYN>>>(
                ph, pl, nullptr, nullptr, curh, curl, nullptr,
                nullptr, hch, hcl, DD, LLEN, 1.0f,
                (long)LLEN * LLEN, (long)LLEN * DD, (long)LLEN * DD);
            // nxt = relu(concat(cur, hidc) @ combW^T + combb)  -> split
            tgemm<1, 1, 1, 0, 1><<<gC, 256, SMEM_DYN>>>(
                curh, curl, hch, hcl, cwh, cwl, combb,
                nullptr, nxth, nxtl, DD, 2 * DD, 1.0f, 0, 0, 0);
        }
    }
    (void)in_sizes; (void)n_in; (void)out_size;
}